// round 7
// baseline (speedup 1.0000x reference)
#include <cuda_runtime.h>
#include <math.h>

#define MAX_DIM 2048     // up to 11 qubits, 16 KB smem
#define THREADS 256

// One CTA per state vector (grid-stride). Amplitudes in smem as complex
// float2. Apply nq single-qubit Rx rotations as butterfly passes instead of
// the dense 2^nq x 2^nq Kronecker matrix. All output writes are capped at
// out_size FLOATS (minimal interpretation of the output buffer), so an
// output-dtype surprise yields rel_err, never an illegal access.
__global__ __launch_bounds__(THREADS)
void rx_layer_kernel(const float* __restrict__ state,
                     const float* __restrict__ weights,
                     float* __restrict__ out,
                     int nvec, int nblocks, int nq, int dim,
                     long stateLimF, long wLimF, long outCapF,
                     int interleaved)
{
    __shared__ __align__(16) float2 amp[MAX_DIM];
    __shared__ float sa[32];
    __shared__ float sb[32];

    const int tid = threadIdx.x;

    for (int vec = blockIdx.x; vec < nvec; vec += gridDim.x) {
        const int bl = vec % nblocks;

        // Load real state (guarded), imag = 0
        const long sbase = (long)vec * dim;
        for (int i = tid; i < dim; i += THREADS) {
            const long gi = sbase + i;
            amp[i] = make_float2((gi < stateLimF) ? state[gi] : 0.0f, 0.0f);
        }

        // Angles for this block: a = cos(w/2), b = sin(w/2)
        if (tid < nq) {
            const long widx = (long)bl * nq + tid;
            const float w = (widx < wLimF) ? weights[widx] : 0.0f;
            float s, c;
            sincosf(w * 0.5f, &s, &c);
            sa[tid] = c;
            sb[tid] = s;
        }
        __syncthreads();

        // Kron chain: factor q acts on bit (nq-1-q) -> stride = 2^(nq-1-q)
        for (int q = 0; q < nq; q++) {
            const int   st   = 1 << (nq - 1 - q);
            const float a    = sa[q];
            const float b    = sb[q];
            const int   half = dim >> 1;
            for (int p = tid; p < half; p += THREADS) {
                const int lo = ((p & ~(st - 1)) << 1) | (p & (st - 1));
                const int hi = lo + st;
                const float2 x = amp[lo];
                const float2 y = amp[hi];
                // x' = a*x - i*b*y ; y' = a*y - i*b*x
                amp[lo] = make_float2(fmaf(a, x.x,  b * y.y),
                                      fmaf(a, x.y, -b * y.x));
                amp[hi] = make_float2(fmaf(a, y.x,  b * x.y),
                                      fmaf(a, y.y, -b * x.x));
            }
            __syncthreads();
        }

        // Store: either interleaved complex (if the buffer can hold it) or
        // real parts only (float32-casted complex). Hard-capped at outCapF.
        if (interleaved) {
            const long obase = 2L * (long)vec * dim;
            for (int i = tid; i < dim; i += THREADS) {
                const long fo = obase + 2L * i;
                if (fo + 1 < outCapF) {
                    out[fo]     = amp[i].x;
                    out[fo + 1] = amp[i].y;
                }
            }
        } else {
            const long obase = (long)vec * dim;
            for (int i = tid; i < dim; i += THREADS) {
                const long fo = obase + i;
                if (fo < outCapF) out[fo] = amp[i].x;
            }
        }
        __syncthreads();
    }
}

extern "C" void kernel_launch(void* const* d_in, const int* in_sizes, int n_in,
                              void* d_out, int out_size)
{
    // State = largest input buffer; weights = next (unit-invariant).
    int si = 0;
    for (int i = 1; i < n_in; i++) if (in_sizes[i] > in_sizes[si]) si = i;
    int wi = (si == 0) ? ((n_in > 1) ? 1 : 0) : 0;

    const float* state   = (const float*)d_in[si];
    const float* weights = (const float*)d_in[wi];
    const long stateE = in_sizes[si];   // documented: element counts
    const long wE     = in_sizes[wi];

    // Derive nq, nvec, nblocks from element counts (R2 logic, verified:
    // picks nq=11, nvec=256, nblocks=8 for the reference shapes).
    int nq = -1, dim = 0, nvec = 0, nblocks = 1;
    for (int q = 1; q <= 20; q++) {
        if (wE <= 0 || wE % q) continue;
        const long d = 1L << q;
        if (d > MAX_DIM || stateE % d) continue;
        const long nv = stateE / d;
        const long nb = wE / q;
        if (nb <= 0 || nv % nb) continue;
        nq = q; dim = (int)d; nvec = (int)nv; nblocks = (int)nb;
    }
    if (nq < 0) {   // degenerate fallback, still fully guarded
        nq = 1; dim = 2;
        nvec = (int)(stateE >= 2 ? stateE / 2 : 1);
        nblocks = 1;
    }

    // Output cap: out_size interpreted as FLOAT count (smallest sane
    // interpretation -> can never overrun). Interleave only if it fits.
    const long outCapF = out_size;
    const int interleaved = (outCapF >= 2L * (long)nvec * dim) ? 1 : 0;

    int grid = nvec < 2048 ? nvec : 2048;
    if (grid < 1) grid = 1;
    rx_layer_kernel<<<grid, THREADS>>>(state, weights, (float*)d_out,
                                       nvec, nblocks, nq, dim,
                                       stateE, wE, outCapF, interleaved);
}

// round 8
// speedup vs baseline: 1.2694x; 1.2694x over previous
#include <cuda_runtime.h>
#include <math.h>

#define MAX_DIM 2048
#define GTHREADS 256

// ---------------- Fast path: nq=11, dim=2048, register/shuffle butterflies.
// Rx factors on distinct qubits commute, so stages may run in any order:
//   bits 0..2  -> per-thread register stages (8 amps/thread)
//   bits 3..7  -> warp shuffle stages (lane-xor butterflies)
//   bits 8..10 -> one smem permute (swap reg-bits <-> warp-bits), 3 register
//                 stages, one smem restore for coalesced stores.
// 512 threads/CTA = 2 vectors/CTA -> 128 CTAs = one wave on 148 SMs.
#define FDIM   2048
#define FNQ    11
#define FTHREADS 512
#define SPAD(n) ((n) + ((n) >> 5))

__global__ __launch_bounds__(FTHREADS)
void rx_fast_kernel(const float* __restrict__ state,
                    const float* __restrict__ weights,
                    float* __restrict__ out,
                    int nvec, int nblocks, int interleaved)
{
    __shared__ float s_ar[SPAD(2 * FDIM - 1) + 1];
    __shared__ float s_ai[SPAD(2 * FDIM - 1) + 1];
    __shared__ float sa[2][FNQ];
    __shared__ float sb[2][FNQ];

    const int t   = threadIdx.x;
    const int vid = t >> 8;          // which of the CTA's 2 vectors
    const int tl  = t & 255;         // thread-in-vector
    const int w   = tl >> 5;         // warp-in-vector   (3 bits)
    const int l   = tl & 31;         // lane             (5 bits)
    const int vec = blockIdx.x * 2 + vid;
    const bool active = (vec < nvec);

    float xr[8], xi[8];

    // Load 8 consecutive amplitudes (real input), imag = 0
    if (active) {
        const float4* s4 = (const float4*)(state + (size_t)vec * FDIM) + tl * 2;
        const float4 v0 = s4[0];
        const float4 v1 = s4[1];
        xr[0] = v0.x; xr[1] = v0.y; xr[2] = v0.z; xr[3] = v0.w;
        xr[4] = v1.x; xr[5] = v1.y; xr[6] = v1.z; xr[7] = v1.w;
    } else {
        #pragma unroll
        for (int j = 0; j < 8; j++) xr[j] = 0.0f;
    }
    #pragma unroll
    for (int j = 0; j < 8; j++) xi[j] = 0.0f;

    // Angles: a = cos(w/2), b = sin(w/2), per vector's block
    if (tl < FNQ && active) {
        const int bl = vec % nblocks;
        float s, c;
        sincosf(weights[bl * FNQ + tl] * 0.5f, &s, &c);
        sa[vid][tl] = c;
        sb[vid][tl] = s;
    }
    __syncthreads();

    // Butterfly update (symmetric for both halves):
    //   new_re = a*my_re + b*partner_im ; new_im = a*my_im - b*partner_re

    // --- Register stages: amplitude bits 0,1,2 (coeff q = 10-bit)
    #pragma unroll
    for (int b = 0; b < 3; b++) {
        const int m = 1 << b;
        const float ca = sa[vid][10 - b];
        const float cb = sb[vid][10 - b];
        #pragma unroll
        for (int j = 0; j < 8; j++) {
            if ((j & m) == 0) {
                const int h = j | m;
                const float lr = xr[j], li = xi[j];
                const float hr = xr[h], hi = xi[h];
                xr[j] = fmaf(ca, lr,  cb * hi);
                xi[j] = fmaf(ca, li, -cb * hr);
                xr[h] = fmaf(ca, hr,  cb * li);
                xi[h] = fmaf(ca, hi, -cb * lr);
            }
        }
    }

    // --- Shuffle stages: amplitude bits 3..7 -> lane bits 0..4
    #pragma unroll
    for (int b = 3; b < 8; b++) {
        const int lanemask = 1 << (b - 3);
        const float ca = sa[vid][10 - b];
        const float cb = sb[vid][10 - b];
        float pr[8], pi[8];
        #pragma unroll
        for (int j = 0; j < 8; j++) {
            pr[j] = __shfl_xor_sync(0xffffffffu, xr[j], lanemask);
            pi[j] = __shfl_xor_sync(0xffffffffu, xi[j], lanemask);
        }
        #pragma unroll
        for (int j = 0; j < 8; j++) {
            const float nr = fmaf(ca, xr[j],  cb * pi[j]);
            const float ni = fmaf(ca, xi[j], -cb * pr[j]);
            xr[j] = nr;
            xi[j] = ni;
        }
    }

    // --- Permute through smem: thread (w,l) reg j: n=(w<<8)|(l<<3)|j
    //     -> reads m=(j<<8)|(l<<3)|w  (reg bits become amplitude bits 8..10)
    #pragma unroll
    for (int j = 0; j < 8; j++) {
        const int n = (vid << 11) | (tl << 3) | j;
        s_ar[SPAD(n)] = xr[j];
        s_ai[SPAD(n)] = xi[j];
    }
    __syncthreads();
    #pragma unroll
    for (int j = 0; j < 8; j++) {
        const int m = (vid << 11) | (j << 8) | (l << 3) | w;
        xr[j] = s_ar[SPAD(m)];
        xi[j] = s_ai[SPAD(m)];
    }

    // --- Register stages: amplitude bits 8,9,10 -> reg bits 0,1,2 (q = 2-rb)
    #pragma unroll
    for (int rb = 0; rb < 3; rb++) {
        const int m = 1 << rb;
        const float ca = sa[vid][2 - rb];
        const float cb = sb[vid][2 - rb];
        #pragma unroll
        for (int j = 0; j < 8; j++) {
            if ((j & m) == 0) {
                const int h = j | m;
                const float lr = xr[j], li = xi[j];
                const float hr = xr[h], hi = xi[h];
                xr[j] = fmaf(ca, lr,  cb * hi);
                xi[j] = fmaf(ca, li, -cb * hr);
                xr[h] = fmaf(ca, hr,  cb * li);
                xi[h] = fmaf(ca, hi, -cb * lr);
            }
        }
    }

    // --- Restore layout (each thread rewrites exactly the slots it read,
    //     so no barrier needed before the writes; one barrier before reread)
    #pragma unroll
    for (int j = 0; j < 8; j++) {
        const int m = (vid << 11) | (j << 8) | (l << 3) | w;
        s_ar[SPAD(m)] = xr[j];
        s_ai[SPAD(m)] = xi[j];
    }
    __syncthreads();
    #pragma unroll
    for (int j = 0; j < 8; j++) {
        const int n = (vid << 11) | (tl << 3) | j;
        xr[j] = s_ar[SPAD(n)];
        xi[j] = s_ai[SPAD(n)];
    }

    // --- Coalesced store
    if (active) {
        if (interleaved) {
            float4* o4 = (float4*)out + (size_t)vec * (FDIM / 2) + tl * 4;
            #pragma unroll
            for (int k = 0; k < 4; k++)
                o4[k] = make_float4(xr[2 * k], xi[2 * k],
                                    xr[2 * k + 1], xi[2 * k + 1]);
        } else {
            float4* o4 = (float4*)out + (size_t)vec * (FDIM / 4) + tl * 2;
            o4[0] = make_float4(xr[0], xr[1], xr[2], xr[3]);
            o4[1] = make_float4(xr[4], xr[5], xr[6], xr[7]);
        }
    }
}

// ---------------- Generic fallback (the R7 passing kernel, fully guarded).
__global__ __launch_bounds__(GTHREADS)
void rx_layer_kernel(const float* __restrict__ state,
                     const float* __restrict__ weights,
                     float* __restrict__ out,
                     int nvec, int nblocks, int nq, int dim,
                     long stateLimF, long wLimF, long outCapF,
                     int interleaved)
{
    __shared__ __align__(16) float2 amp[MAX_DIM];
    __shared__ float sa[32];
    __shared__ float sb[32];

    const int tid = threadIdx.x;

    for (int vec = blockIdx.x; vec < nvec; vec += gridDim.x) {
        const int bl = vec % nblocks;
        const long sbase = (long)vec * dim;
        for (int i = tid; i < dim; i += GTHREADS) {
            const long gi = sbase + i;
            amp[i] = make_float2((gi < stateLimF) ? state[gi] : 0.0f, 0.0f);
        }
        if (tid < nq) {
            const long widx = (long)bl * nq + tid;
            const float w = (widx < wLimF) ? weights[widx] : 0.0f;
            float s, c;
            sincosf(w * 0.5f, &s, &c);
            sa[tid] = c;
            sb[tid] = s;
        }
        __syncthreads();
        for (int q = 0; q < nq; q++) {
            const int   st   = 1 << (nq - 1 - q);
            const float a    = sa[q];
            const float b    = sb[q];
            const int   half = dim >> 1;
            for (int p = tid; p < half; p += GTHREADS) {
                const int lo = ((p & ~(st - 1)) << 1) | (p & (st - 1));
                const int hi = lo + st;
                const float2 x = amp[lo];
                const float2 y = amp[hi];
                amp[lo] = make_float2(fmaf(a, x.x,  b * y.y),
                                      fmaf(a, x.y, -b * y.x));
                amp[hi] = make_float2(fmaf(a, y.x,  b * x.y),
                                      fmaf(a, y.y, -b * x.x));
            }
            __syncthreads();
        }
        if (interleaved) {
            const long obase = 2L * (long)vec * dim;
            for (int i = tid; i < dim; i += GTHREADS) {
                const long fo = obase + 2L * i;
                if (fo + 1 < outCapF) {
                    out[fo]     = amp[i].x;
                    out[fo + 1] = amp[i].y;
                }
            }
        } else {
            const long obase = (long)vec * dim;
            for (int i = tid; i < dim; i += GTHREADS) {
                const long fo = obase + i;
                if (fo < outCapF) out[fo] = amp[i].x;
            }
        }
        __syncthreads();
    }
}

extern "C" void kernel_launch(void* const* d_in, const int* in_sizes, int n_in,
                              void* d_out, int out_size)
{
    // State = largest input buffer; weights = other (unit-invariant pick).
    int si = 0;
    for (int i = 1; i < n_in; i++) if (in_sizes[i] > in_sizes[si]) si = i;
    int wi = (si == 0) ? ((n_in > 1) ? 1 : 0) : 0;

    const float* state   = (const float*)d_in[si];
    const float* weights = (const float*)d_in[wi];
    const long stateE = in_sizes[si];
    const long wE     = in_sizes[wi];

    int nq = -1, dim = 0, nvec = 0, nblocks = 1;
    for (int q = 1; q <= 20; q++) {
        if (wE <= 0 || wE % q) continue;
        const long d = 1L << q;
        if (d > MAX_DIM || stateE % d) continue;
        const long nv = stateE / d;
        const long nb = wE / q;
        if (nb <= 0 || nv % nb) continue;
        nq = q; dim = (int)d; nvec = (int)nv; nblocks = (int)nb;
    }
    if (nq < 0) { nq = 1; dim = 2; nvec = (int)(stateE >= 2 ? stateE / 2 : 1); nblocks = 1; }

    const long outCapF = out_size;   // floats: minimal safe interpretation
    const int interleaved = (outCapF >= 2L * (long)nvec * dim) ? 1 : 0;

    const bool fast = (nq == 11) && (dim == FDIM) && nvec >= 1 &&
                      (stateE == (long)nvec * FDIM) &&
                      (wE == (long)nblocks * FNQ) &&
                      (outCapF >= (long)nvec * FDIM);   // at least real-only fits

    if (fast) {
        const int grid = (nvec + 1) / 2;
        rx_fast_kernel<<<grid, FTHREADS>>>(state, weights, (float*)d_out,
                                           nvec, nblocks, interleaved);
    } else {
        int grid = nvec < 2048 ? nvec : 2048;
        if (grid < 1) grid = 1;
        rx_layer_kernel<<<grid, GTHREADS>>>(state, weights, (float*)d_out,
                                            nvec, nblocks, nq, dim,
                                            stateE, wE, outCapF, interleaved);
    }
}